// round 7
// baseline (speedup 1.0000x reference)
#include <cuda_runtime.h>
#include <cuda_bf16.h>
#include <math.h>

// Problem sizes (fixed by the reference)
#define BB 64      // batch
#define TT 32      // timesteps
#define EE 512     // embed dim
#define HH 512     // hidden
#define H4 2048    // 4*H
#define VV 10000   // vocab

// ---------------- scratch (device globals: allocation-free) ----------------
__device__ __align__(16) float g_X[TT * BB * EE];        // [T][B][E]
__device__ __align__(16) float g_xproj[TT * BB * H4];    // [T][B][4H]
__device__ __align__(16) float g_hseq[TT * BB * HH];     // [T][B][H]
__device__ __align__(16) float g_h[BB * HH];
__device__ __align__(16) float g_c[BB * HH];
__device__ int g_cap64;

// ---------------- captions dtype detection (int32 vs int64) ----------------
// For int64 (values < 10000) every high word is 0; for int32 the odd words
// are random ids. Reads only the first 2048 int32 words (in-bounds either way).
__global__ void detect_cap_kernel(const int* __restrict__ cap32) {
    if (threadIdx.x == 0 && blockIdx.x == 0) {
        int acc = 0;
        for (int i = 0; i < 256; i++) acc |= cap32[2 * i + 1];
        g_cap64 = (acc == 0) ? 1 : 0;
    }
}

// ---------------- build X: t=0 -> features, t>=1 -> embed(captions[:,t]) ----
__global__ void build_x_kernel(const float* __restrict__ feat,
                               const void* __restrict__ cap,
                               const float* __restrict__ embW) {
    int row = blockIdx.x;            // row = t*B + b
    int t = row >> 6;
    int b = row & 63;
    const float* src;
    if (t == 0) {
        src = feat + (size_t)b * EE;
    } else {
        long long idx;
        if (g_cap64) idx = ((const long long*)cap)[b * TT + t];
        else         idx = (long long)((const int*)cap)[b * TT + t];
        src = embW + (size_t)idx * EE;
    }
    float4* dst = (float4*)(g_X + (size_t)row * EE);
    const float4* s4 = (const float4*)src;
    for (int i = threadIdx.x; i < EE / 4; i += blockDim.x) dst[i] = s4[i];
}

// ---------------- SGEMM NT: C[M,N] = A[M,K] * B[N,K]^T (+ biases) ----------
// asel: 0 -> A = g_X, 1 -> A = g_hseq
// mode: 0 -> C row-major [m*N+n]; 1 -> C[(b*T+t)*N+n] with m = t*64+b
#define BM 128
#define BN 128
#define BK 16

// R5: min-blocks=2 forces <=128 regs -> 2 CTAs/SM (was 139 regs, 1 CTA/SM,
// occ 12.5%, fma 38.5%). 16 warps/SM to hide LDS latency.
__global__ __launch_bounds__(256, 2) void sgemm_nt_kernel(
    int asel, const float* __restrict__ Bm,
    const float* __restrict__ bias1, const float* __restrict__ bias2,
    float* __restrict__ C, int M, int N, int K, int mode)
{
    const float* __restrict__ A = (asel == 0) ? g_X : g_hseq;

    // Row stride BM+4 = 132 floats = 528 bytes: 16B multiple, float4-safe.
    __shared__ float As[2][BK][BM + 4];
    __shared__ float Bs[2][BK][BN + 4];

    const int tid = threadIdx.x;
    const int bm = blockIdx.y * BM;
    const int bn = blockIdx.x * BN;

    const int lr = tid >> 2;           // 0..63
    const int lk = (tid & 3) << 2;     // 0,4,8,12

    const int tx = tid & 15;
    const int ty = tid >> 4;

    float acc[8][8];
#pragma unroll
    for (int i = 0; i < 8; i++)
#pragma unroll
        for (int j = 0; j < 8; j++) acc[i][j] = 0.0f;

    float4 ra0, ra1, rb0, rb1;
    const float4 z4 = make_float4(0.f, 0.f, 0.f, 0.f);

#define FETCH(K0)                                                              \
    do {                                                                       \
        ra0 = *(const float4*)(A + (size_t)(bm + lr) * K + (K0) + lk);         \
        ra1 = *(const float4*)(A + (size_t)(bm + lr + 64) * K + (K0) + lk);    \
        int r0_ = bn + lr, r1_ = bn + lr + 64;                                 \
        rb0 = (r0_ < N) ? *(const float4*)(Bm + (size_t)r0_ * K + (K0) + lk) : z4; \
        rb1 = (r1_ < N) ? *(const float4*)(Bm + (size_t)r1_ * K + (K0) + lk) : z4; \
    } while (0)

#define STAGE(BUF)                                                             \
    do {                                                                       \
        As[BUF][lk + 0][lr] = ra0.x; As[BUF][lk + 1][lr] = ra0.y;              \
        As[BUF][lk + 2][lr] = ra0.z; As[BUF][lk + 3][lr] = ra0.w;              \
        As[BUF][lk + 0][lr + 64] = ra1.x; As[BUF][lk + 1][lr + 64] = ra1.y;    \
        As[BUF][lk + 2][lr + 64] = ra1.z; As[BUF][lk + 3][lr + 64] = ra1.w;    \
        Bs[BUF][lk + 0][lr] = rb0.x; Bs[BUF][lk + 1][lr] = rb0.y;              \
        Bs[BUF][lk + 2][lr] = rb0.z; Bs[BUF][lk + 3][lr] = rb0.w;              \
        Bs[BUF][lk + 0][lr + 64] = rb1.x; Bs[BUF][lk + 1][lr + 64] = rb1.y;    \
        Bs[BUF][lk + 2][lr + 64] = rb1.z; Bs[BUF][lk + 3][lr + 64] = rb1.w;    \
    } while (0)

    FETCH(0);
    STAGE(0);
    __syncthreads();

    const int nk = K / BK;
    for (int kt = 0; kt < nk; kt++) {
        if (kt + 1 < nk) FETCH((kt + 1) * BK);
        const int buf = kt & 1;
#pragma unroll
        for (int kk = 0; kk < BK; kk++) {
            float4 a0 = *(const float4*)&As[buf][kk][ty * 8];
            float4 a1 = *(const float4*)&As[buf][kk][ty * 8 + 4];
            float4 b0 = *(const float4*)&Bs[buf][kk][tx * 8];
            float4 b1 = *(const float4*)&Bs[buf][kk][tx * 8 + 4];
            float av[8] = {a0.x, a0.y, a0.z, a0.w, a1.x, a1.y, a1.z, a1.w};
            float bv[8] = {b0.x, b0.y, b0.z, b0.w, b1.x, b1.y, b1.z, b1.w};
#pragma unroll
            for (int i = 0; i < 8; i++)
#pragma unroll
                for (int j = 0; j < 8; j++) acc[i][j] += av[i] * bv[j];
        }
        if (kt + 1 < nk) {
            __syncthreads();
            STAGE((kt + 1) & 1);
            __syncthreads();
        }
    }

#pragma unroll
    for (int i = 0; i < 8; i++) {
        int m = bm + ty * 8 + i;
        int t = m >> 6;
        int b = m & 63;
#pragma unroll
        for (int j = 0; j < 8; j++) {
            int n = bn + tx * 8 + j;
            if (n < N) {
                float v = acc[i][j];
                if (bias1) v += bias1[n];
                if (bias2) v += bias2[n];
                if (mode == 0) C[(size_t)m * N + n] = v;
                else           C[(size_t)(b * TT + t) * N + n] = v;
            }
        }
    }
#undef FETCH
#undef STAGE
}

// ---------------- fused LSTM step (R5): matvec + gates + update, 1 kernel ---
// Block bx (128 blocks) owns hidden units u0 = bx*4 -> 16 gate rows of W_hh
// (rows g*512 + u0 + j, g in 0..3, j in 0..3). Computes
// G[64 batches][16 rows] = h[64,512] @ Wsel^T over full K in smem chunks,
// exchanges gates via smem, applies activations, updates c/h, writes hseq.
// t==0: h=0 (skip matvec), c_old treated as 0 (no zero-state kernel needed).
__global__ __launch_bounds__(256) void lstm_step_kernel(
    const float* __restrict__ Whh, int t)
{
    const int u0 = blockIdx.x * 4;
    const int tid = threadIdx.x;
    const int tx = tid & 15;   // gate-row index r: g = tx>>2, j = tx&3
    const int ty = tid >> 4;   // batch quad: batches 4*ty .. 4*ty+3

    __shared__ float hs[32][68];   // stride 68 floats = 272B (16B multiple)
    __shared__ float ws[32][20];
    __shared__ float gsm[16][68];

    float a0 = 0.f, a1 = 0.f, a2 = 0.f, a3 = 0.f;

    if (t > 0) {
        for (int k0 = 0; k0 < HH; k0 += 32) {
            // h chunk [64 b][32 k] -> hs[kk][b]; warp reads 32 consecutive k
            // of one batch row (coalesced).
            for (int i = tid; i < 64 * 32; i += 256) {
                int b = i >> 5, kk = i & 31;
                hs[kk][b] = g_h[b * HH + k0 + kk];
            }
            // W chunk: 16 selected gate rows x 32 k (each row coalesced).
            for (int i = tid; i < 16 * 32; i += 256) {
                int r = i >> 5, kk = i & 31;
                int grow = (r >> 2) * HH + u0 + (r & 3);
                ws[kk][r] = Whh[(size_t)grow * HH + k0 + kk];
            }
            __syncthreads();
#pragma unroll
            for (int kk = 0; kk < 32; kk++) {
                float w = ws[kk][tx];                        // bcast per tx
                float4 hv = *(const float4*)&hs[kk][ty * 4]; // bcast per ty
                a0 += hv.x * w;
                a1 += hv.y * w;
                a2 += hv.z * w;
                a3 += hv.w * w;
            }
            __syncthreads();
        }
    }

    // exchange: gsm[r][b] so each (b, unit) thread can gather its 4 gates
    gsm[tx][ty * 4 + 0] = a0;
    gsm[tx][ty * 4 + 1] = a1;
    gsm[tx][ty * 4 + 2] = a2;
    gsm[tx][ty * 4 + 3] = a3;
    __syncthreads();

    // 256 threads = 64 batches x 4 units
    const int j = tid & 3;
    const int b = tid >> 2;
    const int u = u0 + j;

    const float* xp = g_xproj + ((size_t)(t * BB + b)) * H4;
    float gi = xp[u]           + gsm[0 * 4 + j][b];
    float gf = xp[HH + u]      + gsm[1 * 4 + j][b];
    float gg = xp[2 * HH + u]  + gsm[2 * 4 + j][b];
    float go = xp[3 * HH + u]  + gsm[3 * 4 + j][b];

    float i_g = 1.0f / (1.0f + expf(-gi));
    float f_g = 1.0f / (1.0f + expf(-gf));
    float g_g = tanhf(gg);
    float o_g = 1.0f / (1.0f + expf(-go));

    const int idx = b * HH + u;
    float c_old = (t > 0) ? g_c[idx] : 0.0f;
    float c = f_g * c_old + i_g * g_g;
    float h = o_g * tanhf(c);
    g_c[idx] = c;
    g_h[idx] = h;
    g_hseq[((size_t)(t * BB + b)) * HH + u] = h;
}

// ---------------- launch ----------------
extern "C" void kernel_launch(void* const* d_in, const int* in_sizes, int n_in,
                              void* d_out, int out_size)
{
    const float* features = (const float*)d_in[0];
    const void*  captions = d_in[1];                 // int32 or int64, detected
    const float* embed_W  = (const float*)d_in[2];
    const float* W_ih     = (const float*)d_in[3];
    const float* W_hh     = (const float*)d_in[4];
    const float* b_ih     = (const float*)d_in[5];
    const float* b_hh     = (const float*)d_in[6];
    const float* fc_W     = (const float*)d_in[7];
    const float* fc_b     = (const float*)d_in[8];
    float* out = (float*)d_out;

    // Resolve device address of g_xproj once (host-side symbol lookup;
    // allocation-free, graph-safe).
    static float* xproj_ptr = nullptr;
    if (!xproj_ptr) {
        void* p = nullptr;
        cudaGetSymbolAddress(&p, g_xproj);
        xproj_ptr = (float*)p;
    }

    detect_cap_kernel<<<1, 32>>>((const int*)captions);
    build_x_kernel<<<TT * BB, 128>>>(features, captions, embed_W);

    // x_proj = X @ W_ih^T + b_ih + b_hh   [T*B, 4H]
    sgemm_nt_kernel<<<dim3(H4 / BN, (TT * BB) / BM), 256>>>(
        0, W_ih, b_ih, b_hh, xproj_ptr, TT * BB, H4, EE, 0);

    // fused recurrence: one kernel per timestep
    for (int t = 0; t < TT; t++)
        lstm_step_kernel<<<128, 256>>>(W_hh, t);

    // logits: out[b][t][v] = h_seq[t][b] . fc_W[v] + fc_b[v]
    sgemm_nt_kernel<<<dim3((VV + BN - 1) / BN, (TT * BB) / BM), 256>>>(
        1, fc_W, fc_b, nullptr, out, TT * BB, VV, HH, 1);
}

// round 8
// speedup vs baseline: 1.1200x; 1.1200x over previous
#include <cuda_runtime.h>
#include <cuda_bf16.h>
#include <math.h>
#include <stdint.h>

// Problem sizes (fixed by the reference)
#define BB 64      // batch
#define TT 32      // timesteps
#define EE 512     // embed dim
#define HH 512     // hidden
#define H4 2048    // 4*H
#define VV 10000   // vocab

// ---------------- scratch (device globals: allocation-free) ----------------
__device__ __align__(16) float g_X[TT * BB * EE];        // [T][B][E]
__device__ __align__(16) float g_xproj[TT * BB * H4];    // [T][B][4H]
__device__ __align__(16) float g_hseq[TT * BB * HH];     // [T][B][H]
__device__ __align__(16) float g_h[BB * HH];
__device__ __align__(16) float g_c[BB * HH];
__device__ int g_cap64;

// ---------------- captions dtype detection (int32 vs int64) ----------------
__global__ void detect_cap_kernel(const int* __restrict__ cap32) {
    if (threadIdx.x == 0 && blockIdx.x == 0) {
        int acc = 0;
        for (int i = 0; i < 256; i++) acc |= cap32[2 * i + 1];
        g_cap64 = (acc == 0) ? 1 : 0;
    }
}

// ---------------- build X: t=0 -> features, t>=1 -> embed(captions[:,t]) ----
__global__ void build_x_kernel(const float* __restrict__ feat,
                               const void* __restrict__ cap,
                               const float* __restrict__ embW) {
    int row = blockIdx.x;            // row = t*B + b
    int t = row >> 6;
    int b = row & 63;
    const float* src;
    if (t == 0) {
        src = feat + (size_t)b * EE;
    } else {
        long long idx;
        if (g_cap64) idx = ((const long long*)cap)[b * TT + t];
        else         idx = (long long)((const int*)cap)[b * TT + t];
        src = embW + (size_t)idx * EE;
    }
    float4* dst = (float4*)(g_X + (size_t)row * EE);
    const float4* s4 = (const float4*)src;
    for (int i = threadIdx.x; i < EE / 4; i += blockDim.x) dst[i] = s4[i];
}

// ---------------- tf32 split-precision GEMM NT (tensor cores) --------------
// C[M,N] = A[M,K] * B[N,K]^T (+bias1 +bias2), fp32 in/out.
// Precision: per-operand split hi=tf32(x), lo=tf32(x-hi); acc += Ah*Bh +
// Ah*Bl + Al*Bh in fp32. Residual ~2^-21 relative — far below 1e-3.
// asel: 0 -> A = g_X, 1 -> A = g_hseq.
// mode: 0 -> C[m*N+n]; 1 -> C[(b*TT+t)*N+n] with m = t*64+b.
// Block: 128 thr / 4 warps; block tile 64x64; warp tile 32x32 (2x4 m16n8k8);
// BK=32; smem stride 36 floats -> frag-load bank = 4*gid+tig = lane (conflict-
// free); 144B row stride is a 16B multiple (float4-safe staging).

__device__ __forceinline__ uint32_t f2tf32(float x) {
    uint32_t r;
    asm("cvt.rna.tf32.f32 %0, %1;" : "=r"(r) : "f"(x));
    return r;
}

__device__ __forceinline__ void mma_tf32(float* d, const uint32_t* a,
                                         const uint32_t* b) {
    asm volatile(
        "mma.sync.aligned.m16n8k8.row.col.f32.tf32.tf32.f32 "
        "{%0,%1,%2,%3}, {%4,%5,%6,%7}, {%8,%9}, {%0,%1,%2,%3};"
        : "+f"(d[0]), "+f"(d[1]), "+f"(d[2]), "+f"(d[3])
        : "r"(a[0]), "r"(a[1]), "r"(a[2]), "r"(a[3]), "r"(b[0]), "r"(b[1]));
}

__global__ __launch_bounds__(128) void tf32_gemm_nt_kernel(
    int asel, const float* __restrict__ Bm,
    const float* __restrict__ bias1, const float* __restrict__ bias2,
    float* __restrict__ C, int M, int N, int K, int mode)
{
    const float* __restrict__ A = (asel == 0) ? g_X : g_hseq;

    __shared__ float As[64][36];
    __shared__ float Bs[64][36];

    const int tid  = threadIdx.x;
    const int lane = tid & 31;
    const int warp = tid >> 5;
    const int wm   = (warp >> 1) * 32;   // warp row offset in block tile
    const int wn   = (warp & 1) * 32;    // warp col offset in block tile
    const int bm   = blockIdx.y * 64;
    const int bn   = blockIdx.x * 64;
    const int gid  = lane >> 2;          // 0..7
    const int tig  = lane & 3;           // 0..3

    float acc[2][4][4];
#pragma unroll
    for (int i = 0; i < 2; i++)
#pragma unroll
        for (int j = 0; j < 4; j++)
#pragma unroll
            for (int q = 0; q < 4; q++) acc[i][j][q] = 0.0f;

    const float4 z4 = make_float4(0.f, 0.f, 0.f, 0.f);

    for (int k0 = 0; k0 < K; k0 += 32) {
        __syncthreads();
        // stage A[64][32] and B[64][32] (fp32). Coalesced: 8 consecutive tid
        // cover one 128B row segment.
#pragma unroll
        for (int it = 0; it < 4; it++) {
            int idx = tid + it * 128;        // 0..511
            int row = idx >> 3;
            int kc  = (idx & 7) * 4;
            *(float4*)&As[row][kc] =
                *(const float4*)(A + (size_t)(bm + row) * K + k0 + kc);
            int nrow = bn + row;
            float4 bv = (nrow < N)
                ? *(const float4*)(Bm + (size_t)nrow * K + k0 + kc) : z4;
            *(float4*)&Bs[row][kc] = bv;
        }
        __syncthreads();

#pragma unroll
        for (int ks = 0; ks < 32; ks += 8) {
            // A fragments (2 m16 tiles), hi/lo
            uint32_t ah[2][4], al[2][4];
#pragma unroll
            for (int i = 0; i < 2; i++) {
                float x0 = As[wm + i * 16 + gid][ks + tig];
                float x1 = As[wm + i * 16 + gid + 8][ks + tig];
                float x2 = As[wm + i * 16 + gid][ks + tig + 4];
                float x3 = As[wm + i * 16 + gid + 8][ks + tig + 4];
                ah[i][0] = f2tf32(x0); al[i][0] = f2tf32(x0 - __uint_as_float(ah[i][0]));
                ah[i][1] = f2tf32(x1); al[i][1] = f2tf32(x1 - __uint_as_float(ah[i][1]));
                ah[i][2] = f2tf32(x2); al[i][2] = f2tf32(x2 - __uint_as_float(ah[i][2]));
                ah[i][3] = f2tf32(x3); al[i][3] = f2tf32(x3 - __uint_as_float(ah[i][3]));
            }
            // B fragments (4 n8 tiles), hi/lo. Bs is [n][k]; b0 = B[k=tig][n=gid].
            uint32_t bh[4][2], bl[4][2];
#pragma unroll
            for (int j = 0; j < 4; j++) {
                float y0 = Bs[wn + j * 8 + gid][ks + tig];
                float y1 = Bs[wn + j * 8 + gid][ks + tig + 4];
                bh[j][0] = f2tf32(y0); bl[j][0] = f2tf32(y0 - __uint_as_float(bh[j][0]));
                bh[j][1] = f2tf32(y1); bl[j][1] = f2tf32(y1 - __uint_as_float(bh[j][1]));
            }
#pragma unroll
            for (int i = 0; i < 2; i++)
#pragma unroll
                for (int j = 0; j < 4; j++) {
                    mma_tf32(acc[i][j], ah[i], bh[j]);  // hi*hi
                    mma_tf32(acc[i][j], ah[i], bl[j]);  // hi*lo
                    mma_tf32(acc[i][j], al[i], bh[j]);  // lo*hi
                }
        }
    }

    // epilogue. C frag mapping: c0=(gid, 2*tig), c1=(gid, 2*tig+1),
    // c2=(gid+8, 2*tig), c3=(gid+8, 2*tig+1) within each m16n8 tile.
#pragma unroll
    for (int i = 0; i < 2; i++) {
#pragma unroll
        for (int j = 0; j < 4; j++) {
#pragma unroll
            for (int q = 0; q < 4; q++) {
                int m = bm + wm + i * 16 + gid + (q >= 2 ? 8 : 0);
                int n = bn + wn + j * 8 + tig * 2 + (q & 1);
                if (n < N) {
                    float v = acc[i][j][q];
                    if (bias1) v += bias1[n];
                    if (bias2) v += bias2[n];
                    if (mode == 0) {
                        C[(size_t)m * N + n] = v;
                    } else {
                        int t = m >> 6, b = m & 63;
                        C[(size_t)(b * TT + t) * N + n] = v;
                    }
                }
            }
        }
    }
}

// ---------------- fused LSTM step: matvec + gates + update, 1 kernel -------
// Block bx (128 blocks) owns hidden units u0 = bx*4 -> 16 gate rows of W_hh.
__global__ __launch_bounds__(256) void lstm_step_kernel(
    const float* __restrict__ Whh, int t)
{
    const int u0 = blockIdx.x * 4;
    const int tid = threadIdx.x;
    const int tx = tid & 15;   // gate-row index r: g = tx>>2, j = tx&3
    const int ty = tid >> 4;   // batch quad: batches 4*ty .. 4*ty+3

    __shared__ float hs[32][68];   // stride 68 floats = 272B (16B multiple)
    __shared__ float ws[32][20];
    __shared__ float gsm[16][68];

    float a0 = 0.f, a1 = 0.f, a2 = 0.f, a3 = 0.f;

    if (t > 0) {
        for (int k0 = 0; k0 < HH; k0 += 32) {
            for (int i = tid; i < 64 * 32; i += 256) {
                int b = i >> 5, kk = i & 31;
                hs[kk][b] = g_h[b * HH + k0 + kk];
            }
            for (int i = tid; i < 16 * 32; i += 256) {
                int r = i >> 5, kk = i & 31;
                int grow = (r >> 2) * HH + u0 + (r & 3);
                ws[kk][r] = Whh[(size_t)grow * HH + k0 + kk];
            }
            __syncthreads();
#pragma unroll
            for (int kk = 0; kk < 32; kk++) {
                float w = ws[kk][tx];
                float4 hv = *(const float4*)&hs[kk][ty * 4];
                a0 += hv.x * w;
                a1 += hv.y * w;
                a2 += hv.z * w;
                a3 += hv.w * w;
            }
            __syncthreads();
        }
    }

    gsm[tx][ty * 4 + 0] = a0;
    gsm[tx][ty * 4 + 1] = a1;
    gsm[tx][ty * 4 + 2] = a2;
    gsm[tx][ty * 4 + 3] = a3;
    __syncthreads();

    const int j = tid & 3;
    const int b = tid >> 2;
    const int u = u0 + j;

    const float* xp = g_xproj + ((size_t)(t * BB + b)) * H4;
    float gi = xp[u]           + gsm[0 * 4 + j][b];
    float gf = xp[HH + u]      + gsm[1 * 4 + j][b];
    float gg = xp[2 * HH + u]  + gsm[2 * 4 + j][b];
    float go = xp[3 * HH + u]  + gsm[3 * 4 + j][b];

    float i_g = 1.0f / (1.0f + expf(-gi));
    float f_g = 1.0f / (1.0f + expf(-gf));
    float g_g = tanhf(gg);
    float o_g = 1.0f / (1.0f + expf(-go));

    const int idx = b * HH + u;
    float c_old = (t > 0) ? g_c[idx] : 0.0f;
    float c = f_g * c_old + i_g * g_g;
    float h = o_g * tanhf(c);
    g_c[idx] = c;
    g_h[idx] = h;
    g_hseq[((size_t)(t * BB + b)) * HH + u] = h;
}

// ---------------- launch ----------------
extern "C" void kernel_launch(void* const* d_in, const int* in_sizes, int n_in,
                              void* d_out, int out_size)
{
    const float* features = (const float*)d_in[0];
    const void*  captions = d_in[1];                 // int32 or int64, detected
    const float* embed_W  = (const float*)d_in[2];
    const float* W_ih     = (const float*)d_in[3];
    const float* W_hh     = (const float*)d_in[4];
    const float* b_ih     = (const float*)d_in[5];
    const float* b_hh     = (const float*)d_in[6];
    const float* fc_W     = (const float*)d_in[7];
    const float* fc_b     = (const float*)d_in[8];
    float* out = (float*)d_out;

    static float* xproj_ptr = nullptr;
    if (!xproj_ptr) {
        void* p = nullptr;
        cudaGetSymbolAddress(&p, g_xproj);
        xproj_ptr = (float*)p;
    }

    detect_cap_kernel<<<1, 32>>>((const int*)captions);
    build_x_kernel<<<TT * BB, 128>>>(features, captions, embed_W);

    // x_proj = X @ W_ih^T + b_ih + b_hh   [T*B, 4H]   (tf32 tensor cores)
    tf32_gemm_nt_kernel<<<dim3(H4 / 64, (TT * BB) / 64), 128>>>(
        0, W_ih, b_ih, b_hh, xproj_ptr, TT * BB, H4, EE, 0);

    // fused recurrence: one kernel per timestep
    for (int t = 0; t < TT; t++)
        lstm_step_kernel<<<128, 256>>>(W_hh, t);

    // logits: out[b][t][v] = h_seq[t][b] . fc_W[v] + fc_b[v]  (tf32)
    tf32_gemm_nt_kernel<<<dim3((VV + 63) / 64, (TT * BB) / 64), 128>>>(
        1, fc_W, fc_b, nullptr, out, TT * BB, VV, HH, 1);
}

// round 9
// speedup vs baseline: 1.1768x; 1.0507x over previous
#include <cuda_runtime.h>
#include <cuda_fp16.h>
#include <math.h>
#include <stdint.h>

// Problem sizes (fixed by the reference)
#define BB 64      // batch
#define TT 32      // timesteps
#define EE 512     // embed dim
#define HH 512     // hidden
#define H4 2048    // 4*H
#define VV 10000   // vocab
#define KP 1536    // augmented K' = 3*512 (fp16 split folded into K)

// ---------------- scratch (device globals: allocation-free) ----------------
__device__ __align__(16) float g_X[TT * BB * EE];        // [T][B][E]
__device__ __align__(16) float g_xproj[TT * BB * H4];    // [T][B][4H]
__device__ __align__(16) float g_hseq[TT * BB * HH];     // [T][B][H]
__device__ __align__(16) float g_h[BB * HH];
__device__ __align__(16) float g_c[BB * HH];
// fp16 split-augmented operands (hi/hi/lo for A-side, hi/lo/hi for B-side)
__device__ __align__(16) __half g_Xs[(size_t)H4 * KP];     // A' for x_proj  [2048][1536]
__device__ __align__(16) __half g_Hs[(size_t)H4 * KP];     // A' for logits  [2048][1536]
__device__ __align__(16) __half g_Wihs[(size_t)H4 * KP];   // B' W_ih        [2048][1536]
__device__ __align__(16) __half g_Fcs[(size_t)VV * KP];    // B' fc_W        [10000][1536]
__device__ int g_cap64;

// ---------------- captions dtype detection (int32 vs int64) ----------------
__global__ void detect_cap_kernel(const int* __restrict__ cap32) {
    if (threadIdx.x == 0 && blockIdx.x == 0) {
        int acc = 0;
        for (int i = 0; i < 256; i++) acc |= cap32[2 * i + 1];
        g_cap64 = (acc == 0) ? 1 : 0;
    }
}

// ---------------- build X: t=0 -> features, t>=1 -> embed(captions[:,t]) ----
__global__ void build_x_kernel(const float* __restrict__ feat,
                               const void* __restrict__ cap,
                               const float* __restrict__ embW) {
    int row = blockIdx.x;            // row = t*B + b
    int t = row >> 6;
    int b = row & 63;
    const float* src;
    if (t == 0) {
        src = feat + (size_t)b * EE;
    } else {
        long long idx;
        if (g_cap64) idx = ((const long long*)cap)[b * TT + t];
        else         idx = (long long)((const int*)cap)[b * TT + t];
        src = embW + (size_t)idx * EE;
    }
    float4* dst = (float4*)(g_X + (size_t)row * EE);
    const float4* s4 = (const float4*)src;
    for (int i = threadIdx.x; i < EE / 4; i += blockDim.x) dst[i] = s4[i];
}

// ---------------- fp16 split conversion (offline, K-augmented) -------------
// For source element i (rows contiguous, K=512 -> K'=1536, so dst off = 3*i):
//   pat 0 (A-side): (hi, hi, lo);  pat 1 (B-side): (hi, lo, hi)
// C = sum over K' of A'*B' = Ah*Bh + Ah*Bl + Al*Bh. Residual ~2^-22 relative.
__global__ void conv_split_kernel(const float* __restrict__ src,
                                  __half* __restrict__ dst, int n, int pat) {
    int i = blockIdx.x * blockDim.x + threadIdx.x;
    if (i >= n) return;
    float x = src[i];
    __half hi = __float2half_rn(x);
    __half lo = __float2half_rn(x - __half2float(hi));
    size_t o = (size_t)i * 3;
    if (pat == 0) { dst[o] = hi; dst[o + 1] = hi; dst[o + 2] = lo; }
    else          { dst[o] = hi; dst[o + 1] = lo; dst[o + 2] = hi; }
}

// ---------------- fp16 HGEMM NT (tensor cores, fp32 accumulate) ------------
// C[M,N] = A'[M,KP] * B'[N,KP]^T (+bias1 +bias2), halves in, fp32 out.
// mode 0: C[m*N+n]; mode 1: C[(b*TT+t)*N+n], m = t*64+b.
// 256 thr / 8 warps; block tile 128x128; warp tile 32x64 (2x8 m16n8k16);
// BK=64 halves. Smem stride 72 halves = 36 words: frag-load bank =
// (36*row + tig) % 32 = 4*gid + tig = lane -> conflict-free.
#define GBM 128
#define GBN 128
#define GBK 64

__device__ __forceinline__ void mma_f16(float* d, const uint32_t* a,
                                        const uint32_t* b) {
    asm volatile(
        "mma.sync.aligned.m16n8k16.row.col.f32.f16.f16.f32 "
        "{%0,%1,%2,%3}, {%4,%5,%6,%7}, {%8,%9}, {%0,%1,%2,%3};"
        : "+f"(d[0]), "+f"(d[1]), "+f"(d[2]), "+f"(d[3])
        : "r"(a[0]), "r"(a[1]), "r"(a[2]), "r"(a[3]), "r"(b[0]), "r"(b[1]));
}

__global__ __launch_bounds__(256) void hgemm_nt_kernel(
    const __half* __restrict__ A, const __half* __restrict__ Bm,
    const float* __restrict__ bias1, const float* __restrict__ bias2,
    float* __restrict__ C, int M, int N, int mode)
{
    __shared__ __half As[GBM][GBK + 8];
    __shared__ __half Bs[GBN][GBK + 8];

    const int tid  = threadIdx.x;
    const int lane = tid & 31;
    const int warp = tid >> 5;
    const int wm   = (warp >> 1) * 32;   // 4 warps along M
    const int wn   = (warp & 1) * 64;    // 2 warps along N
    const int bm   = blockIdx.y * GBM;
    const int bn   = blockIdx.x * GBN;
    const int gid  = lane >> 2;          // 0..7
    const int tig  = lane & 3;           // 0..3

    float acc[2][8][4];
#pragma unroll
    for (int i = 0; i < 2; i++)
#pragma unroll
        for (int j = 0; j < 8; j++)
#pragma unroll
            for (int q = 0; q < 4; q++) acc[i][j][q] = 0.0f;

    const uint4 z4 = make_uint4(0, 0, 0, 0);

#pragma unroll 1
    for (int k0 = 0; k0 < KP; k0 += GBK) {
        __syncthreads();
        // stage A'[128][64] and B'[128][64] halves; 8 halves (16B) per load.
#pragma unroll
        for (int it = 0; it < 4; it++) {
            int idx = tid + it * 256;        // 0..1023
            int row = idx >> 3;              // 0..127
            int kc  = (idx & 7) * 8;         // 0..56
            *(uint4*)&As[row][kc] =
                *(const uint4*)(A + (size_t)(bm + row) * KP + k0 + kc);
            int nr = bn + row;
            *(uint4*)&Bs[row][kc] = (nr < N)
                ? *(const uint4*)(Bm + (size_t)nr * KP + k0 + kc) : z4;
        }
        __syncthreads();

#pragma unroll
        for (int ks = 0; ks < GBK; ks += 16) {
            uint32_t af[2][4];
#pragma unroll
            for (int i = 0; i < 2; i++) {
                int r = wm + i * 16 + gid;
                af[i][0] = *(const uint32_t*)&As[r][ks + 2 * tig];
                af[i][1] = *(const uint32_t*)&As[r + 8][ks + 2 * tig];
                af[i][2] = *(const uint32_t*)&As[r][ks + 8 + 2 * tig];
                af[i][3] = *(const uint32_t*)&As[r + 8][ks + 8 + 2 * tig];
            }
#pragma unroll
            for (int j = 0; j < 8; j++) {
                uint32_t bf[2];
                int r = wn + j * 8 + gid;
                bf[0] = *(const uint32_t*)&Bs[r][ks + 2 * tig];
                bf[1] = *(const uint32_t*)&Bs[r][ks + 8 + 2 * tig];
#pragma unroll
                for (int i = 0; i < 2; i++) mma_f16(acc[i][j], af[i], bf);
            }
        }
    }

    // epilogue: c0=(gid,2tig), c1=(gid,2tig+1), c2/c3 = row+8
#pragma unroll
    for (int i = 0; i < 2; i++) {
#pragma unroll
        for (int j = 0; j < 8; j++) {
#pragma unroll
            for (int q = 0; q < 4; q++) {
                int m = bm + wm + i * 16 + gid + (q >= 2 ? 8 : 0);
                int n = bn + wn + j * 8 + tig * 2 + (q & 1);
                if (n < N) {
                    float v = acc[i][j][q];
                    if (bias1) v += bias1[n];
                    if (bias2) v += bias2[n];
                    if (mode == 0) {
                        C[(size_t)m * N + n] = v;
                    } else {
                        int t = m >> 6, b = m & 63;
                        C[(size_t)(b * TT + t) * N + n] = v;
                    }
                }
            }
        }
    }
}

// ---------------- fused LSTM step: matvec + gates + update, 1 kernel -------
__global__ __launch_bounds__(256) void lstm_step_kernel(
    const float* __restrict__ Whh, int t)
{
    const int u0 = blockIdx.x * 4;
    const int tid = threadIdx.x;
    const int tx = tid & 15;   // gate-row index r: g = tx>>2, j = tx&3
    const int ty = tid >> 4;   // batch quad

    __shared__ float hs[32][68];
    __shared__ float ws[32][20];
    __shared__ float gsm[16][68];

    float a0 = 0.f, a1 = 0.f, a2 = 0.f, a3 = 0.f;

    if (t > 0) {
        for (int k0 = 0; k0 < HH; k0 += 32) {
            for (int i = tid; i < 64 * 32; i += 256) {
                int b = i >> 5, kk = i & 31;
                hs[kk][b] = g_h[b * HH + k0 + kk];
            }
            for (int i = tid; i < 16 * 32; i += 256) {
                int r = i >> 5, kk = i & 31;
                int grow = (r >> 2) * HH + u0 + (r & 3);
                ws[kk][r] = Whh[(size_t)grow * HH + k0 + kk];
            }
            __syncthreads();
#pragma unroll
            for (int kk = 0; kk < 32; kk++) {
                float w = ws[kk][tx];
                float4 hv = *(const float4*)&hs[kk][ty * 4];
                a0 += hv.x * w;
                a1 += hv.y * w;
                a2 += hv.z * w;
                a3 += hv.w * w;
            }
            __syncthreads();
        }
    }

    gsm[tx][ty * 4 + 0] = a0;
    gsm[tx][ty * 4 + 1] = a1;
    gsm[tx][ty * 4 + 2] = a2;
    gsm[tx][ty * 4 + 3] = a3;
    __syncthreads();

    const int j = tid & 3;
    const int b = tid >> 2;
    const int u = u0 + j;

    const float* xp = g_xproj + ((size_t)(t * BB + b)) * H4;
    float gi = xp[u]           + gsm[0 * 4 + j][b];
    float gf = xp[HH + u]      + gsm[1 * 4 + j][b];
    float gg = xp[2 * HH + u]  + gsm[2 * 4 + j][b];
    float go = xp[3 * HH + u]  + gsm[3 * 4 + j][b];

    float i_g = 1.0f / (1.0f + expf(-gi));
    float f_g = 1.0f / (1.0f + expf(-gf));
    float g_g = tanhf(gg);
    float o_g = 1.0f / (1.0f + expf(-go));

    const int idx = b * HH + u;
    float c_old = (t > 0) ? g_c[idx] : 0.0f;
    float c = f_g * c_old + i_g * g_g;
    float h = o_g * tanhf(c);
    g_c[idx] = c;
    g_h[idx] = h;
    g_hseq[((size_t)(t * BB + b)) * HH + u] = h;
}

// ---------------- launch ----------------
extern "C" void kernel_launch(void* const* d_in, const int* in_sizes, int n_in,
                              void* d_out, int out_size)
{
    const float* features = (const float*)d_in[0];
    const void*  captions = d_in[1];                 // int32 or int64, detected
    const float* embed_W  = (const float*)d_in[2];
    const float* W_ih     = (const float*)d_in[3];
    const float* W_hh     = (const float*)d_in[4];
    const float* b_ih     = (const float*)d_in[5];
    const float* b_hh     = (const float*)d_in[6];
    const float* fc_W     = (const float*)d_in[7];
    const float* fc_b     = (const float*)d_in[8];
    float* out = (float*)d_out;

    // Resolve device-global scratch addresses once (host-side, graph-safe).
    static float *xproj_p = nullptr, *X_p = nullptr, *hseq_p = nullptr;
    static __half *Xs_p = nullptr, *Hs_p = nullptr, *Wihs_p = nullptr,
                  *Fcs_p = nullptr;
    if (!xproj_p) {
        void* p;
        cudaGetSymbolAddress(&p, g_xproj); xproj_p = (float*)p;
        cudaGetSymbolAddress(&p, g_X);     X_p     = (float*)p;
        cudaGetSymbolAddress(&p, g_hseq);  hseq_p  = (float*)p;
        cudaGetSymbolAddress(&p, g_Xs);    Xs_p    = (__half*)p;
        cudaGetSymbolAddress(&p, g_Hs);    Hs_p    = (__half*)p;
        cudaGetSymbolAddress(&p, g_Wihs);  Wihs_p  = (__half*)p;
        cudaGetSymbolAddress(&p, g_Fcs);   Fcs_p   = (__half*)p;
    }

    detect_cap_kernel<<<1, 32>>>((const int*)captions);
    build_x_kernel<<<TT * BB, 128>>>(features, captions, embed_W);

    // offline fp16 split conversions
    conv_split_kernel<<<(H4 * EE + 255) / 256, 256>>>(X_p, Xs_p, H4 * EE, 0);
    conv_split_kernel<<<(H4 * EE + 255) / 256, 256>>>(W_ih, Wihs_p, H4 * EE, 1);
    conv_split_kernel<<<(VV * HH + 255) / 256, 256>>>(fc_W, Fcs_p, VV * HH, 1);

    // x_proj = X @ W_ih^T + b_ih + b_hh   [T*B, 4H]   (fp16-split tensor cores)
    hgemm_nt_kernel<<<dim3(H4 / GBN, (TT * BB) / GBM), 256>>>(
        Xs_p, Wihs_p, b_ih, b_hh, xproj_p, TT * BB, H4, 0);

    // fused recurrence: one kernel per timestep
    for (int t = 0; t < TT; t++)
        lstm_step_kernel<<<128, 256>>>(W_hh, t);

    // convert h_seq, then logits GEMM
    conv_split_kernel<<<(H4 * HH + 255) / 256, 256>>>(hseq_p, Hs_p, H4 * HH, 0);
    hgemm_nt_kernel<<<dim3((VV + GBN - 1) / GBN, (TT * BB) / GBM), 256>>>(
        Hs_p, Fcs_p, fc_b, nullptr, out, TT * BB, VV, 1);
}